// round 2
// baseline (speedup 1.0000x reference)
#include <cuda_runtime.h>
#include <math_constants.h>

// Problem constants (fixed by setup_inputs)
#define BB   4
#define SS   2048
#define DD   1024
#define HH   16
#define HDIM 64
#define MTOK (BB * SS)          // 8192 tokens

// Scratch buffers (static device globals: allocation-free, graph-capturable)
__device__ float g_q[MTOK * DD];
__device__ float g_k[MTOK * DD];
__device__ float g_v[MTOK * DD];
__device__ float g_o[MTOK * DD];

// ---------------------------------------------------------------------------
// C[m,n] = sum_k A[m,k] * W[n,k]  (+ bias[n])       ("x @ W.T" torch Linear)
// 64x64 block tile, BK=16, 256 threads, 4x4 per thread.
// ---------------------------------------------------------------------------
template <bool BIAS>
__global__ __launch_bounds__(256)
void gemm_nt(const float* __restrict__ A, const float* __restrict__ W,
             const float* __restrict__ bias, float* __restrict__ C,
             int M, int N, int K)
{
    __shared__ float As[16][68];   // [k][m]  (68 keeps float4 rows 16B-aligned)
    __shared__ float Ws[16][68];   // [k][n]

    const int tid = threadIdx.x;
    const int tx  = tid & 15;       // 0..15 -> n sub-tile
    const int ty  = tid >> 4;       // 0..15 -> m sub-tile
    const int mb  = blockIdx.y << 6;
    const int nb  = blockIdx.x << 6;
    const int lr  = tid >> 2;       // 0..63  load row
    const int lc  = (tid & 3) << 2; // 0,4,8,12 load col (float4)

    float acc[4][4] = {};

    for (int k0 = 0; k0 < K; k0 += 16) {
        float4 av = *(const float4*)(A + (size_t)(mb + lr) * K + k0 + lc);
        float4 wv = *(const float4*)(W + (size_t)(nb + lr) * K + k0 + lc);
        __syncthreads();
        As[lc + 0][lr] = av.x; As[lc + 1][lr] = av.y;
        As[lc + 2][lr] = av.z; As[lc + 3][lr] = av.w;
        Ws[lc + 0][lr] = wv.x; Ws[lc + 1][lr] = wv.y;
        Ws[lc + 2][lr] = wv.z; Ws[lc + 3][lr] = wv.w;
        __syncthreads();
#pragma unroll
        for (int k = 0; k < 16; k++) {
            float4 a = *(const float4*)&As[k][ty << 2];
            float4 w = *(const float4*)&Ws[k][tx << 2];
            float ar[4] = {a.x, a.y, a.z, a.w};
            float wr[4] = {w.x, w.y, w.z, w.w};
#pragma unroll
            for (int i = 0; i < 4; i++)
#pragma unroll
                for (int j = 0; j < 4; j++)
                    acc[i][j] = fmaf(ar[i], wr[j], acc[i][j]);
        }
    }

    const int col = nb + (tx << 2);
    float b4[4] = {0.f, 0.f, 0.f, 0.f};
    if (BIAS) {
        b4[0] = bias[col + 0]; b4[1] = bias[col + 1];
        b4[2] = bias[col + 2]; b4[3] = bias[col + 3];
    }
#pragma unroll
    for (int i = 0; i < 4; i++) {
        const int row = mb + (ty << 2) + i;
        float4 o;
        o.x = acc[i][0] + b4[0];
        o.y = acc[i][1] + b4[1];
        o.z = acc[i][2] + b4[2];
        o.w = acc[i][3] + b4[3];
        *(float4*)(C + (size_t)row * N + col) = o;
    }
}

// ---------------------------------------------------------------------------
// Flash-attention forward, fp32, head_dim=64.
// One CTA per (batch, head, 64-row Q tile). 256 threads as 16x16; 4x4 patch
// per thread for both the 64x64 score tile and the 64x64 output tile.
// Online softmax in log2 domain: p = exp2(s*(1/32)*log2e - m).
// Smem: Qt[d][r], Kt[d][c] (reused as P^T[c][r]), Vs[c][d]; stride 68.
// ---------------------------------------------------------------------------
__global__ __launch_bounds__(256)
void attn_fwd(const float* __restrict__ Q, const float* __restrict__ Kv,
              const float* __restrict__ V, float* __restrict__ O)
{
    extern __shared__ float sm[];
    float* Qt = sm;                  // 64 x 68, transposed: Qt[d*68 + r]
    float* Kt = sm + 64 * 68;        // K^T then reused as P^T
    float* Vs = sm + 2 * 64 * 68;    // Vs[c*68 + d]

    const int tid = threadIdx.x;
    const int tx  = tid & 15;
    const int ty  = tid >> 4;
    const int q0  = blockIdx.x << 6;
    const int h   = blockIdx.y;
    const int b   = blockIdx.z;
    const size_t hb = (size_t)b * SS * DD + (size_t)h * HDIM;

    const int rr = tid >> 4;          // 0..15 loader row
    const int d4 = (tid & 15) << 2;   // 0..60 loader dim (float4)

    // Load Q tile, transposed
#pragma unroll
    for (int p = 0; p < 4; p++) {
        const int r = (p << 4) + rr;
        float4 qv = *(const float4*)(Q + hb + (size_t)(q0 + r) * DD + d4);
        Qt[(d4 + 0) * 68 + r] = qv.x;
        Qt[(d4 + 1) * 68 + r] = qv.y;
        Qt[(d4 + 2) * 68 + r] = qv.z;
        Qt[(d4 + 3) * 68 + r] = qv.w;
    }

    float m[4], l[4], acc[4][4];
#pragma unroll
    for (int i = 0; i < 4; i++) {
        m[i] = -CUDART_INF_F; l[i] = 0.f;
#pragma unroll
        for (int j = 0; j < 4; j++) acc[i][j] = 0.f;
    }
    const float sc = 0.03125f * 1.44269504088896340736f;  // (1/32)*log2(e)

    for (int t = 0; t < SS / 64; t++) {
        const int kv0 = t << 6;
        __syncthreads();   // prev P@V done (and Q load visible on t=0)
#pragma unroll
        for (int p = 0; p < 4; p++) {
            const int r = (p << 4) + rr;
            float4 kv = *(const float4*)(Kv + hb + (size_t)(kv0 + r) * DD + d4);
            float4 vv = *(const float4*)(V  + hb + (size_t)(kv0 + r) * DD + d4);
            Kt[(d4 + 0) * 68 + r] = kv.x;
            Kt[(d4 + 1) * 68 + r] = kv.y;
            Kt[(d4 + 2) * 68 + r] = kv.z;
            Kt[(d4 + 3) * 68 + r] = kv.w;
            *(float4*)&Vs[r * 68 + d4] = vv;
        }
        __syncthreads();

        // S = Q @ K^T (4x4 patch per thread)
        float s[4][4] = {};
#pragma unroll 4
        for (int d = 0; d < 64; d++) {
            float4 a = *(const float4*)&Qt[d * 68 + (ty << 2)];
            float4 k = *(const float4*)&Kt[d * 68 + (tx << 2)];
            float ar[4] = {a.x, a.y, a.z, a.w};
            float kr[4] = {k.x, k.y, k.z, k.w};
#pragma unroll
            for (int i = 0; i < 4; i++)
#pragma unroll
                for (int j = 0; j < 4; j++)
                    s[i][j] = fmaf(ar[i], kr[j], s[i][j]);
        }

        // Row max over this tile (reduce across the 16 tx lanes)
        float mt[4];
#pragma unroll
        for (int i = 0; i < 4; i++) {
            s[i][0] *= sc; s[i][1] *= sc; s[i][2] *= sc; s[i][3] *= sc;
            mt[i] = fmaxf(fmaxf(s[i][0], s[i][1]), fmaxf(s[i][2], s[i][3]));
        }
#pragma unroll
        for (int off = 8; off; off >>= 1)
#pragma unroll
            for (int i = 0; i < 4; i++)
                mt[i] = fmaxf(mt[i], __shfl_xor_sync(0xffffffffu, mt[i], off));

        // Online softmax update
        float pv_[4][4];
#pragma unroll
        for (int i = 0; i < 4; i++) {
            const float mnew = fmaxf(m[i], mt[i]);
            const float corr = exp2f(m[i] - mnew);   // exp2(-inf)=0 first tile
            m[i] = mnew;
            float rs = 0.f;
#pragma unroll
            for (int j = 0; j < 4; j++) {
                pv_[i][j] = exp2f(s[i][j] - mnew);
                rs += pv_[i][j];
            }
            l[i] = l[i] * corr + rs;   // partial over own 4 cols; reduced later
#pragma unroll
            for (int j = 0; j < 4; j++) acc[i][j] *= corr;
        }

        __syncthreads();   // everyone done reading Kt
        // Write P^T into the Kt buffer
#pragma unroll
        for (int j = 0; j < 4; j++)
#pragma unroll
            for (int i = 0; i < 4; i++)
                Kt[((tx << 2) + j) * 68 + (ty << 2) + i] = pv_[i][j];
        __syncthreads();

        // O += P @ V
#pragma unroll 4
        for (int c = 0; c < 64; c++) {
            float4 a = *(const float4*)&Kt[c * 68 + (ty << 2)];
            float4 v = *(const float4*)&Vs[c * 68 + (tx << 2)];
            float ar[4] = {a.x, a.y, a.z, a.w};
            float vr[4] = {v.x, v.y, v.z, v.w};
#pragma unroll
            for (int i = 0; i < 4; i++)
#pragma unroll
                for (int j = 0; j < 4; j++)
                    acc[i][j] = fmaf(ar[i], vr[j], acc[i][j]);
        }
    }

    // Reduce the row-sum l across the 16 tx lanes
#pragma unroll
    for (int off = 8; off; off >>= 1)
#pragma unroll
        for (int i = 0; i < 4; i++)
            l[i] += __shfl_xor_sync(0xffffffffu, l[i], off);

#pragma unroll
    for (int i = 0; i < 4; i++) {
        const float inv = 1.f / l[i];
        float4 o;
        o.x = acc[i][0] * inv; o.y = acc[i][1] * inv;
        o.z = acc[i][2] * inv; o.w = acc[i][3] * inv;
        *(float4*)(O + hb + (size_t)(q0 + (ty << 2) + i) * DD + (tx << 2)) = o;
    }
}

// ---------------------------------------------------------------------------
extern "C" void kernel_launch(void* const* d_in, const int* in_sizes, int n_in,
                              void* d_out, int out_size)
{
    const float* values = (const float*)d_in[0];
    const float* keys   = (const float*)d_in[1];
    const float* query  = (const float*)d_in[2];
    const float* Wv     = (const float*)d_in[3];
    const float* Wk     = (const float*)d_in[4];
    const float* Wq     = (const float*)d_in[5];
    const float* Wo     = (const float*)d_in[6];
    const float* bo     = (const float*)d_in[7];
    float* out = (float*)d_out;

    float *pq, *pk, *pv, *po;
    cudaGetSymbolAddress((void**)&pq, g_q);
    cudaGetSymbolAddress((void**)&pk, g_k);
    cudaGetSymbolAddress((void**)&pv, g_v);
    cudaGetSymbolAddress((void**)&po, g_o);

    const int attn_smem = 3 * 64 * 68 * (int)sizeof(float);  // 52224 B
    cudaFuncSetAttribute(attn_fwd, cudaFuncAttributeMaxDynamicSharedMemorySize,
                         attn_smem);

    dim3 blk(256);
    dim3 gp(DD / 64, MTOK / 64);        // (16, 128)

    gemm_nt<false><<<gp, blk>>>(query,  Wq, nullptr, pq, MTOK, DD, DD);
    gemm_nt<false><<<gp, blk>>>(keys,   Wk, nullptr, pk, MTOK, DD, DD);
    gemm_nt<false><<<gp, blk>>>(values, Wv, nullptr, pv, MTOK, DD, DD);

    dim3 ga(SS / 64, HH, BB);           // (32, 16, 4)
    attn_fwd<<<ga, blk, attn_smem>>>(pq, pk, pv, po);

    gemm_nt<true><<<gp, blk>>>(po, Wo, bo, out, MTOK, DD, DD);
}

// round 5
// speedup vs baseline: 1.4588x; 1.4588x over previous
#include <cuda_runtime.h>
#include <cuda_bf16.h>
#include <math_constants.h>
#include <cstdint>

// Problem constants (fixed by setup_inputs)
#define BB   4
#define SS   2048
#define DD   1024
#define HH   16
#define HDIM 64
#define MTOK (BB * SS)          // 8192 tokens

// ---------------------------------------------------------------------------
// Scratch (static device globals: allocation-free, graph-capturable)
// ---------------------------------------------------------------------------
__device__ float g_q[MTOK * DD];
__device__ float g_k[MTOK * DD];
__device__ float g_v[MTOK * DD];
__device__ float g_o[MTOK * DD];
__device__ __align__(16) __nv_bfloat16 g_ahi[MTOK * DD];
__device__ __align__(16) __nv_bfloat16 g_alo[MTOK * DD];
__device__ __align__(16) __nv_bfloat16 g_whi[4 * DD * DD];
__device__ __align__(16) __nv_bfloat16 g_wlo[4 * DD * DD];

// ---------------------------------------------------------------------------
// Base-ISA helpers (sm_103 base target: mma.sync / ldmatrix / cp.async only —
// tcgen05 is an 'a'-feature and is rejected by this build's ptxas target)
// ---------------------------------------------------------------------------
__device__ __forceinline__ uint32_t smem_u32(const void* p) {
    uint32_t a;
    asm("{ .reg .u64 t; cvta.to.shared.u64 t, %1; cvt.u32.u64 %0, t; }"
        : "=r"(a) : "l"(p));
    return a;
}

__device__ __forceinline__ void ldsm4(uint32_t (&r)[4], uint32_t addr) {
    asm volatile("ldmatrix.sync.aligned.m8n8.x4.shared.b16 {%0,%1,%2,%3}, [%4];"
                 : "=r"(r[0]), "=r"(r[1]), "=r"(r[2]), "=r"(r[3]) : "r"(addr));
}

__device__ __forceinline__ void mma16816(float (&d)[4], const uint32_t (&a)[4],
                                         uint32_t b0, uint32_t b1) {
    asm volatile(
        "mma.sync.aligned.m16n8k16.row.col.f32.bf16.bf16.f32 "
        "{%0,%1,%2,%3}, {%4,%5,%6,%7}, {%8,%9}, {%0,%1,%2,%3};"
        : "+f"(d[0]), "+f"(d[1]), "+f"(d[2]), "+f"(d[3])
        : "r"(a[0]), "r"(a[1]), "r"(a[2]), "r"(a[3]), "r"(b0), "r"(b1));
}

__device__ __forceinline__ void cp16(uint32_t saddr, const void* g) {
    asm volatile("cp.async.cg.shared.global [%0], [%1], 16;"
                 :: "r"(saddr), "l"(g) : "memory");
}
#define CP_COMMIT() asm volatile("cp.async.commit_group;" ::: "memory")
#define CP_WAIT0()  asm volatile("cp.async.wait_group 0;" ::: "memory")

// ---------------------------------------------------------------------------
// fp32 -> bf16 hi/lo split (elementwise)
// ---------------------------------------------------------------------------
__global__ __launch_bounds__(256)
void split_f32(const float* __restrict__ x, __nv_bfloat16* __restrict__ hi,
               __nv_bfloat16* __restrict__ lo, int n4)
{
    int i = blockIdx.x * blockDim.x + threadIdx.x;
    if (i >= n4) return;
    float4 v = ((const float4*)x)[i];
    float vv[4] = {v.x, v.y, v.z, v.w};
    __nv_bfloat16 h[4], l[4];
#pragma unroll
    for (int j = 0; j < 4; j++) {
        h[j] = __float2bfloat16(vv[j]);
        l[j] = __float2bfloat16(vv[j] - __bfloat162float(h[j]));
    }
    __nv_bfloat162 h0; h0.x = h[0]; h0.y = h[1];
    __nv_bfloat162 h1; h1.x = h[2]; h1.y = h[3];
    __nv_bfloat162 l0; l0.x = l[0]; l0.y = l[1];
    __nv_bfloat162 l1; l1.x = l[2]; l1.y = l[3];
    ((__nv_bfloat162*)hi)[i * 2 + 0] = h0;
    ((__nv_bfloat162*)hi)[i * 2 + 1] = h1;
    ((__nv_bfloat162*)lo)[i * 2 + 0] = l0;
    ((__nv_bfloat162*)lo)[i * 2 + 1] = l1;
}

// ---------------------------------------------------------------------------
// mma.sync split-bf16 GEMM:  C[m,n] = sum_k A[m,k]*W[n,k] (+bias[n])
// CTA tile 128x128, 8 warps (2m x 4n), warp tile 64x32, K chunk = 32 bf16.
// D += Ahi*Whi + Ahi*Wlo + Alo*Whi (fp32 accumulate in registers).
// Smem rows: 32 bf16 = 64B padded to 80B (conflict-free ldmatrix).
// Double-buffered cp.async.
// ---------------------------------------------------------------------------
#define TPAD        80
#define TILE_BYTES  (128 * TPAD)        // 10240
#define STAGE_BYTES (4 * TILE_BYTES)    // 40960
#define GEMM_SMEM   (2 * STAGE_BYTES)   // 81920
#define NKC         (DD / 32)           // 32 chunks

template <bool BIAS>
__global__ __launch_bounds__(256)
void gemm_mma(const __nv_bfloat16* __restrict__ Ahi, const __nv_bfloat16* __restrict__ Alo,
              const __nv_bfloat16* __restrict__ Whi, const __nv_bfloat16* __restrict__ Wlo,
              const float* __restrict__ bias, float* __restrict__ C)
{
    extern __shared__ char smem[];
    const uint32_t sb = smem_u32(smem);

    const int tid   = threadIdx.x;
    const int lane  = tid & 31;
    const int wid   = tid >> 5;
    const int warpM = wid >> 2;          // 0..1
    const int warpN = wid & 3;           // 0..3
    const int m0 = blockIdx.y << 7;
    const int n0 = blockIdx.x << 7;

    // Loader mapping: 64 rows x 4 16B-units per pass, 2 passes per tile
    const int lrow = tid >> 2;           // 0..63
    const int lu   = tid & 3;            // 0..3

    const __nv_bfloat16* srcs[4] = {Ahi, Alo, Whi, Wlo};

    auto load_stage = [&](int kc, int st) {
        const uint32_t stb = sb + st * STAGE_BYTES;
#pragma unroll
        for (int t = 0; t < 4; t++) {
            const int base_row = (t < 2) ? m0 : n0;
#pragma unroll
            for (int p = 0; p < 2; p++) {
                const int row = lrow + (p << 6);
                const __nv_bfloat16* g =
                    srcs[t] + (size_t)(base_row + row) * DD + kc * 32 + lu * 8;
                cp16(stb + t * TILE_BYTES + row * TPAD + lu * 16, g);
            }
        }
        CP_COMMIT();
    };

    float d[4][4][4];                    // [mf][nf][4]
#pragma unroll
    for (int mf = 0; mf < 4; mf++)
#pragma unroll
        for (int nf = 0; nf < 4; nf++)
#pragma unroll
            for (int e = 0; e < 4; e++) d[mf][nf][e] = 0.f;

    load_stage(0, 0);

    // ldmatrix address components (constant across chunks)
    const int arow  = warpM * 64 + (lane & 15);          // + mf*16
    const uint32_t akoff = (uint32_t)((lane >> 4) << 4); // + s*32
    const int mi    = lane >> 3;
    const int nrow  = warpN * 32 + ((mi >> 1) << 3) + (lane & 7);  // + nfp*16
    const uint32_t bkoff = (uint32_t)((mi & 1) << 4);

    for (int kc = 0; kc < NKC; kc++) {
        CP_WAIT0();
        __syncthreads();
        if (kc + 1 < NKC) load_stage(kc + 1, (kc + 1) & 1);

        const uint32_t stb = sb + (kc & 1) * STAGE_BYTES;
#pragma unroll
        for (int s = 0; s < 2; s++) {
            uint32_t ahi[4][4], alo[4][4];
#pragma unroll
            for (int mf = 0; mf < 4; mf++) {
                const uint32_t aoff =
                    (uint32_t)((arow + mf * 16) * TPAD) + s * 32 + akoff;
                ldsm4(ahi[mf], stb + 0 * TILE_BYTES + aoff);
                ldsm4(alo[mf], stb + 1 * TILE_BYTES + aoff);
            }
            uint32_t bhi[2][4], blo[2][4];
#pragma unroll
            for (int nfp = 0; nfp < 2; nfp++) {
                const uint32_t boff =
                    (uint32_t)((nrow + nfp * 16) * TPAD) + s * 32 + bkoff;
                ldsm4(bhi[nfp], stb + 2 * TILE_BYTES + boff);
                ldsm4(blo[nfp], stb + 3 * TILE_BYTES + boff);
            }
#pragma unroll
            for (int mf = 0; mf < 4; mf++) {
#pragma unroll
                for (int nf = 0; nf < 4; nf++) {
                    const int p = nf >> 1, q = (nf & 1) << 1;
                    mma16816(d[mf][nf], ahi[mf], bhi[p][q], bhi[p][q + 1]);
                    mma16816(d[mf][nf], ahi[mf], blo[p][q], blo[p][q + 1]);
                    mma16816(d[mf][nf], alo[mf], bhi[p][q], bhi[p][q + 1]);
                }
            }
        }
        __syncthreads();
    }

    // Epilogue
#pragma unroll
    for (int mf = 0; mf < 4; mf++) {
        const int gm = m0 + warpM * 64 + mf * 16 + (lane >> 2);
#pragma unroll
        for (int nf = 0; nf < 4; nf++) {
            const int gn = n0 + warpN * 32 + nf * 8 + ((lane & 3) << 1);
            float2 v0 = make_float2(d[mf][nf][0], d[mf][nf][1]);
            float2 v1 = make_float2(d[mf][nf][2], d[mf][nf][3]);
            if (BIAS) {
                const float b0 = bias[gn], b1 = bias[gn + 1];
                v0.x += b0; v0.y += b1;
                v1.x += b0; v1.y += b1;
            }
            *(float2*)(C + (size_t)gm * DD + gn)       = v0;
            *(float2*)(C + (size_t)(gm + 8) * DD + gn) = v1;
        }
    }
}

// ---------------------------------------------------------------------------
// Flash-attention forward, fp32, head_dim=64 (unchanged; known-good 1.9ms).
// ---------------------------------------------------------------------------
__global__ __launch_bounds__(256)
void attn_fwd(const float* __restrict__ Q, const float* __restrict__ Kv,
              const float* __restrict__ V, float* __restrict__ O)
{
    extern __shared__ float sm[];
    float* Qt = sm;                  // 64 x 68 transposed
    float* Kt = sm + 64 * 68;        // K^T then reused as P^T
    float* Vs = sm + 2 * 64 * 68;    // Vs[c*68 + d]

    const int tid = threadIdx.x;
    const int tx  = tid & 15;
    const int ty  = tid >> 4;
    const int q0  = blockIdx.x << 6;
    const int h   = blockIdx.y;
    const int b   = blockIdx.z;
    const size_t hb = (size_t)b * SS * DD + (size_t)h * HDIM;

    const int rr = tid >> 4;
    const int d4 = (tid & 15) << 2;

#pragma unroll
    for (int p = 0; p < 4; p++) {
        const int r = (p << 4) + rr;
        float4 qv = *(const float4*)(Q + hb + (size_t)(q0 + r) * DD + d4);
        Qt[(d4 + 0) * 68 + r] = qv.x;
        Qt[(d4 + 1) * 68 + r] = qv.y;
        Qt[(d4 + 2) * 68 + r] = qv.z;
        Qt[(d4 + 3) * 68 + r] = qv.w;
    }

    float m[4], l[4], acc[4][4];
#pragma unroll
    for (int i = 0; i < 4; i++) {
        m[i] = -CUDART_INF_F; l[i] = 0.f;
#pragma unroll
        for (int j = 0; j < 4; j++) acc[i][j] = 0.f;
    }
    const float sc = 0.03125f * 1.44269504088896340736f;

    for (int t = 0; t < SS / 64; t++) {
        const int kv0 = t << 6;
        __syncthreads();
#pragma unroll
        for (int p = 0; p < 4; p++) {
            const int r = (p << 4) + rr;
            float4 kv = *(const float4*)(Kv + hb + (size_t)(kv0 + r) * DD + d4);
            float4 vv = *(const float4*)(V  + hb + (size_t)(kv0 + r) * DD + d4);
            Kt[(d4 + 0) * 68 + r] = kv.x;
            Kt[(d4 + 1) * 68 + r] = kv.y;
            Kt[(d4 + 2) * 68 + r] = kv.z;
            Kt[(d4 + 3) * 68 + r] = kv.w;
            *(float4*)&Vs[r * 68 + d4] = vv;
        }
        __syncthreads();

        float s[4][4] = {};
#pragma unroll 4
        for (int d = 0; d < 64; d++) {
            float4 a = *(const float4*)&Qt[d * 68 + (ty << 2)];
            float4 k = *(const float4*)&Kt[d * 68 + (tx << 2)];
            float ar[4] = {a.x, a.y, a.z, a.w};
            float kr[4] = {k.x, k.y, k.z, k.w};
#pragma unroll
            for (int i = 0; i < 4; i++)
#pragma unroll
                for (int j = 0; j < 4; j++)
                    s[i][j] = fmaf(ar[i], kr[j], s[i][j]);
        }

        float mt[4];
#pragma unroll
        for (int i = 0; i < 4; i++) {
            s[i][0] *= sc; s[i][1] *= sc; s[i][2] *= sc; s[i][3] *= sc;
            mt[i] = fmaxf(fmaxf(s[i][0], s[i][1]), fmaxf(s[i][2], s[i][3]));
        }
#pragma unroll
        for (int off = 8; off; off >>= 1)
#pragma unroll
            for (int i = 0; i < 4; i++)
                mt[i] = fmaxf(mt[i], __shfl_xor_sync(0xffffffffu, mt[i], off));

        float pv_[4][4];
#pragma unroll
        for (int i = 0; i < 4; i++) {
            const float mnew = fmaxf(m[i], mt[i]);
            const float corr = exp2f(m[i] - mnew);
            m[i] = mnew;
            float rs = 0.f;
#pragma unroll
            for (int j = 0; j < 4; j++) {
                pv_[i][j] = exp2f(s[i][j] - mnew);
                rs += pv_[i][j];
            }
            l[i] = l[i] * corr + rs;
#pragma unroll
            for (int j = 0; j < 4; j++) acc[i][j] *= corr;
        }

        __syncthreads();
#pragma unroll
        for (int j = 0; j < 4; j++)
#pragma unroll
            for (int i = 0; i < 4; i++)
                Kt[((tx << 2) + j) * 68 + (ty << 2) + i] = pv_[i][j];
        __syncthreads();

#pragma unroll 4
        for (int c = 0; c < 64; c++) {
            float4 a = *(const float4*)&Kt[c * 68 + (ty << 2)];
            float4 v = *(const float4*)&Vs[c * 68 + (tx << 2)];
            float ar[4] = {a.x, a.y, a.z, a.w};
            float vr[4] = {v.x, v.y, v.z, v.w};
#pragma unroll
            for (int i = 0; i < 4; i++)
#pragma unroll
                for (int j = 0; j < 4; j++)
                    acc[i][j] = fmaf(ar[i], vr[j], acc[i][j]);
        }
    }

#pragma unroll
    for (int off = 8; off; off >>= 1)
#pragma unroll
        for (int i = 0; i < 4; i++)
            l[i] += __shfl_xor_sync(0xffffffffu, l[i], off);

#pragma unroll
    for (int i = 0; i < 4; i++) {
        const float inv = 1.f / l[i];
        float4 o;
        o.x = acc[i][0] * inv; o.y = acc[i][1] * inv;
        o.z = acc[i][2] * inv; o.w = acc[i][3] * inv;
        *(float4*)(O + hb + (size_t)(q0 + (ty << 2) + i) * DD + (tx << 2)) = o;
    }
}

// ---------------------------------------------------------------------------
extern "C" void kernel_launch(void* const* d_in, const int* in_sizes, int n_in,
                              void* d_out, int out_size)
{
    const float* values = (const float*)d_in[0];
    const float* keys   = (const float*)d_in[1];
    const float* query  = (const float*)d_in[2];
    const float* Wv     = (const float*)d_in[3];
    const float* Wk     = (const float*)d_in[4];
    const float* Wq     = (const float*)d_in[5];
    const float* Wo     = (const float*)d_in[6];
    const float* bo     = (const float*)d_in[7];
    float* out = (float*)d_out;

    float *pq, *pk, *pv, *po;
    __nv_bfloat16 *ahi, *alo, *whi, *wlo;
    cudaGetSymbolAddress((void**)&pq, g_q);
    cudaGetSymbolAddress((void**)&pk, g_k);
    cudaGetSymbolAddress((void**)&pv, g_v);
    cudaGetSymbolAddress((void**)&po, g_o);
    cudaGetSymbolAddress((void**)&ahi, g_ahi);
    cudaGetSymbolAddress((void**)&alo, g_alo);
    cudaGetSymbolAddress((void**)&whi, g_whi);
    cudaGetSymbolAddress((void**)&wlo, g_wlo);

    const int attn_smem = 3 * 64 * 68 * (int)sizeof(float);
    cudaFuncSetAttribute(attn_fwd, cudaFuncAttributeMaxDynamicSharedMemorySize,
                         attn_smem);
    cudaFuncSetAttribute(gemm_mma<false>,
                         cudaFuncAttributeMaxDynamicSharedMemorySize, GEMM_SMEM);
    cudaFuncSetAttribute(gemm_mma<true>,
                         cudaFuncAttributeMaxDynamicSharedMemorySize, GEMM_SMEM);

    const int W4 = DD * DD / 4;       // float4 count per weight
    const int A4 = MTOK * DD / 4;

    // Split all weights once
    split_f32<<<W4 / 256, 256>>>(Wq, whi + 0 * DD * DD, wlo + 0 * DD * DD, W4);
    split_f32<<<W4 / 256, 256>>>(Wk, whi + 1 * DD * DD, wlo + 1 * DD * DD, W4);
    split_f32<<<W4 / 256, 256>>>(Wv, whi + 2 * DD * DD, wlo + 2 * DD * DD, W4);
    split_f32<<<W4 / 256, 256>>>(Wo, whi + 3 * DD * DD, wlo + 3 * DD * DD, W4);

    dim3 gg(DD / 128, MTOK / 128);    // (8, 64)

    split_f32<<<A4 / 256, 256>>>(query, ahi, alo, A4);
    gemm_mma<false><<<gg, 256, GEMM_SMEM>>>(ahi, alo, whi + 0 * DD * DD,
                                            wlo + 0 * DD * DD, nullptr, pq);
    split_f32<<<A4 / 256, 256>>>(keys, ahi, alo, A4);
    gemm_mma<false><<<gg, 256, GEMM_SMEM>>>(ahi, alo, whi + 1 * DD * DD,
                                            wlo + 1 * DD * DD, nullptr, pk);
    split_f32<<<A4 / 256, 256>>>(values, ahi, alo, A4);
    gemm_mma<false><<<gg, 256, GEMM_SMEM>>>(ahi, alo, whi + 2 * DD * DD,
                                            wlo + 2 * DD * DD, nullptr, pv);

    dim3 ga(SS / 64, HH, BB);
    attn_fwd<<<ga, 256, attn_smem>>>(pq, pk, pv, po);

    split_f32<<<A4 / 256, 256>>>(po, ahi, alo, A4);
    gemm_mma<true><<<gg, 256, GEMM_SMEM>>>(ahi, alo, whi + 3 * DD * DD,
                                           wlo + 3 * DD * DD, bo, out);
}

// round 7
// speedup vs baseline: 3.1836x; 2.1823x over previous
#include <cuda_runtime.h>
#include <cuda_bf16.h>
#include <math_constants.h>
#include <cstdint>

// Problem constants (fixed by setup_inputs)
#define BB   4
#define SS   2048
#define DD   1024
#define HH   16
#define HDIM 64
#define MTOK (BB * SS)          // 8192 tokens

// ---------------------------------------------------------------------------
// Scratch (static device globals: allocation-free, graph-capturable)
// ---------------------------------------------------------------------------
__device__ __align__(16) __nv_bfloat16 g_ahi[MTOK * DD];   // input split / attn out hi
__device__ __align__(16) __nv_bfloat16 g_alo[MTOK * DD];   // input split / attn out lo
__device__ __align__(16) __nv_bfloat16 g_whi[4 * DD * DD];
__device__ __align__(16) __nv_bfloat16 g_wlo[4 * DD * DD];
__device__ __align__(16) __nv_bfloat16 g_qhi[MTOK * DD];
__device__ __align__(16) __nv_bfloat16 g_qlo[MTOK * DD];
__device__ __align__(16) __nv_bfloat16 g_khi[MTOK * DD];
__device__ __align__(16) __nv_bfloat16 g_klo[MTOK * DD];
__device__ __align__(16) __nv_bfloat16 g_vhi[MTOK * DD];
__device__ __align__(16) __nv_bfloat16 g_vlo[MTOK * DD];

// ---------------------------------------------------------------------------
// Base-ISA helpers (sm_103 base target; tcgen05 is ptxas-rejected here)
// ---------------------------------------------------------------------------
__device__ __forceinline__ uint32_t smem_u32(const void* p) {
    uint32_t a;
    asm("{ .reg .u64 t; cvta.to.shared.u64 t, %1; cvt.u32.u64 %0, t; }"
        : "=r"(a) : "l"(p));
    return a;
}
__device__ __forceinline__ void ldsm4(uint32_t (&r)[4], uint32_t addr) {
    asm volatile("ldmatrix.sync.aligned.m8n8.x4.shared.b16 {%0,%1,%2,%3}, [%4];"
                 : "=r"(r[0]), "=r"(r[1]), "=r"(r[2]), "=r"(r[3]) : "r"(addr));
}
__device__ __forceinline__ void ldsm4t(uint32_t (&r)[4], uint32_t addr) {
    asm volatile("ldmatrix.sync.aligned.m8n8.x4.trans.shared.b16 {%0,%1,%2,%3}, [%4];"
                 : "=r"(r[0]), "=r"(r[1]), "=r"(r[2]), "=r"(r[3]) : "r"(addr));
}
__device__ __forceinline__ void mma16816(float (&d)[4], const uint32_t (&a)[4],
                                         uint32_t b0, uint32_t b1) {
    asm volatile(
        "mma.sync.aligned.m16n8k16.row.col.f32.bf16.bf16.f32 "
        "{%0,%1,%2,%3}, {%4,%5,%6,%7}, {%8,%9}, {%0,%1,%2,%3};"
        : "+f"(d[0]), "+f"(d[1]), "+f"(d[2]), "+f"(d[3])
        : "r"(a[0]), "r"(a[1]), "r"(a[2]), "r"(a[3]), "r"(b0), "r"(b1));
}
__device__ __forceinline__ void cp16(uint32_t saddr, const void* g) {
    asm volatile("cp.async.cg.shared.global [%0], [%1], 16;"
                 :: "r"(saddr), "l"(g) : "memory");
}
#define CP_COMMIT() asm volatile("cp.async.commit_group;" ::: "memory")
#define CP_WAIT0()  asm volatile("cp.async.wait_group 0;" ::: "memory")

__device__ __forceinline__ uint32_t pack_bf162(float lo, float hi) {
    __nv_bfloat162 h = __floats2bfloat162_rn(lo, hi);
    return *reinterpret_cast<uint32_t*>(&h);
}

// ---------------------------------------------------------------------------
// fp32 -> bf16 hi/lo split (elementwise)
// ---------------------------------------------------------------------------
__global__ __launch_bounds__(256)
void split_f32(const float* __restrict__ x, __nv_bfloat16* __restrict__ hi,
               __nv_bfloat16* __restrict__ lo, int n4)
{
    int i = blockIdx.x * blockDim.x + threadIdx.x;
    if (i >= n4) return;
    float4 v = ((const float4*)x)[i];
    float vv[4] = {v.x, v.y, v.z, v.w};
    __nv_bfloat16 h[4], l[4];
#pragma unroll
    for (int j = 0; j < 4; j++) {
        h[j] = __float2bfloat16(vv[j]);
        l[j] = __float2bfloat16(vv[j] - __bfloat162float(h[j]));
    }
    __nv_bfloat162 h0; h0.x = h[0]; h0.y = h[1];
    __nv_bfloat162 h1; h1.x = h[2]; h1.y = h[3];
    __nv_bfloat162 l0; l0.x = l[0]; l0.y = l[1];
    __nv_bfloat162 l1; l1.x = l[2]; l1.y = l[3];
    ((__nv_bfloat162*)hi)[i * 2 + 0] = h0;
    ((__nv_bfloat162*)hi)[i * 2 + 1] = h1;
    ((__nv_bfloat162*)lo)[i * 2 + 0] = l0;
    ((__nv_bfloat162*)lo)[i * 2 + 1] = l1;
}

// ---------------------------------------------------------------------------
// mma.sync split-bf16 GEMM:  C[m,n] = sum_k A[m,k]*W[n,k] (+bias[n])
// CTA tile 128x128, 8 warps (2m x 4n), warp tile 64x32, K chunk = 32 bf16.
// SPLIT: write hi/lo bf16 outputs instead of fp32.
// ---------------------------------------------------------------------------
#define TPAD        80
#define TILE_BYTES  (128 * TPAD)        // 10240
#define STAGE_BYTES (4 * TILE_BYTES)    // 40960
#define GEMM_SMEM   (2 * STAGE_BYTES)   // 81920
#define NKC         (DD / 32)           // 32 chunks

template <bool BIAS, bool SPLIT>
__global__ __launch_bounds__(256)
void gemm_mma(const __nv_bfloat16* __restrict__ Ahi, const __nv_bfloat16* __restrict__ Alo,
              const __nv_bfloat16* __restrict__ Whi, const __nv_bfloat16* __restrict__ Wlo,
              const float* __restrict__ bias, float* __restrict__ C,
              __nv_bfloat16* __restrict__ Chi, __nv_bfloat16* __restrict__ Clo)
{
    extern __shared__ char smem[];
    const uint32_t sb = smem_u32(smem);

    const int tid   = threadIdx.x;
    const int lane  = tid & 31;
    const int wid   = tid >> 5;
    const int warpM = wid >> 2;
    const int warpN = wid & 3;
    const int m0 = blockIdx.y << 7;
    const int n0 = blockIdx.x << 7;

    const int lrow = tid >> 2;
    const int lu   = tid & 3;

    const __nv_bfloat16* srcs[4] = {Ahi, Alo, Whi, Wlo};

    auto load_stage = [&](int kc, int st) {
        const uint32_t stb = sb + st * STAGE_BYTES;
#pragma unroll
        for (int t = 0; t < 4; t++) {
            const int base_row = (t < 2) ? m0 : n0;
#pragma unroll
            for (int p = 0; p < 2; p++) {
                const int row = lrow + (p << 6);
                const __nv_bfloat16* g =
                    srcs[t] + (size_t)(base_row + row) * DD + kc * 32 + lu * 8;
                cp16(stb + t * TILE_BYTES + row * TPAD + lu * 16, g);
            }
        }
        CP_COMMIT();
    };

    float d[4][4][4];
#pragma unroll
    for (int mf = 0; mf < 4; mf++)
#pragma unroll
        for (int nf = 0; nf < 4; nf++)
#pragma unroll
            for (int e = 0; e < 4; e++) d[mf][nf][e] = 0.f;

    load_stage(0, 0);

    const int arow  = warpM * 64 + (lane & 15);
    const uint32_t akoff = (uint32_t)((lane >> 4) << 4);
    const int mi    = lane >> 3;
    const int nrow  = warpN * 32 + ((mi >> 1) << 3) + (lane & 7);
    const uint32_t bkoff = (uint32_t)((mi & 1) << 4);

    for (int kc = 0; kc < NKC; kc++) {
        CP_WAIT0();
        __syncthreads();
        if (kc + 1 < NKC) load_stage(kc + 1, (kc + 1) & 1);

        const uint32_t stb = sb + (kc & 1) * STAGE_BYTES;
#pragma unroll
        for (int s = 0; s < 2; s++) {
            uint32_t ahi[4][4], alo[4][4];
#pragma unroll
            for (int mf = 0; mf < 4; mf++) {
                const uint32_t aoff =
                    (uint32_t)((arow + mf * 16) * TPAD) + s * 32 + akoff;
                ldsm4(ahi[mf], stb + 0 * TILE_BYTES + aoff);
                ldsm4(alo[mf], stb + 1 * TILE_BYTES + aoff);
            }
            uint32_t bhi[2][4], blo[2][4];
#pragma unroll
            for (int nfp = 0; nfp < 2; nfp++) {
                const uint32_t boff =
                    (uint32_t)((nrow + nfp * 16) * TPAD) + s * 32 + bkoff;
                ldsm4(bhi[nfp], stb + 2 * TILE_BYTES + boff);
                ldsm4(blo[nfp], stb + 3 * TILE_BYTES + boff);
            }
#pragma unroll
            for (int mf = 0; mf < 4; mf++) {
#pragma unroll
                for (int nf = 0; nf < 4; nf++) {
                    const int p = nf >> 1, q = (nf & 1) << 1;
                    mma16816(d[mf][nf], ahi[mf], bhi[p][q], bhi[p][q + 1]);
                    mma16816(d[mf][nf], ahi[mf], blo[p][q], blo[p][q + 1]);
                    mma16816(d[mf][nf], alo[mf], bhi[p][q], bhi[p][q + 1]);
                }
            }
        }
        __syncthreads();
    }

    // Epilogue
#pragma unroll
    for (int mf = 0; mf < 4; mf++) {
        const int gm = m0 + warpM * 64 + mf * 16 + (lane >> 2);
#pragma unroll
        for (int nf = 0; nf < 4; nf++) {
            const int gn = n0 + warpN * 32 + nf * 8 + ((lane & 3) << 1);
            if (SPLIT) {
#pragma unroll
                for (int hrow = 0; hrow < 2; hrow++) {
                    const size_t off = (size_t)(gm + hrow * 8) * DD + gn;
                    const float v0 = d[mf][nf][hrow * 2 + 0];
                    const float v1 = d[mf][nf][hrow * 2 + 1];
                    const float h0 = __bfloat162float(__float2bfloat16(v0));
                    const float h1 = __bfloat162float(__float2bfloat16(v1));
                    *(uint32_t*)(Chi + off) = pack_bf162(v0, v1);
                    *(uint32_t*)(Clo + off) = pack_bf162(v0 - h0, v1 - h1);
                }
            } else {
                float2 v0 = make_float2(d[mf][nf][0], d[mf][nf][1]);
                float2 v1 = make_float2(d[mf][nf][2], d[mf][nf][3]);
                if (BIAS) {
                    const float b0 = bias[gn], b1 = bias[gn + 1];
                    v0.x += b0; v0.y += b1;
                    v1.x += b0; v1.y += b1;
                }
                *(float2*)(C + (size_t)gm * DD + gn)       = v0;
                *(float2*)(C + (size_t)(gm + 8) * DD + gn) = v1;
            }
        }
    }
}

// ---------------------------------------------------------------------------
// Flash attention on mma.sync, split-bf16 QK^T and P,V.
// CTA: 128 Q rows for one (b,h). KV tiles of 64, cp.async double-buffered.
// 8 warps, each 16 Q rows. Writes output split (hi/lo bf16) for O-projection.
// Smem rows padded to 144B (conflict-free ldmatrix, 16B-aligned cp.async).
// ---------------------------------------------------------------------------
#define PADB  144
#define SQH   0
#define SQL   (128 * PADB)                 // 18432
#define SKV   (2 * 128 * PADB)             // 36864
#define KVT   (64 * PADB)                  // 9216 per array
#define STG   (4 * KVT)                    // 36864 per stage
#define ATTN_SMEM (SKV + 2 * STG)          // 110592
#define NT    (SS / 64)                    // 32 kv tiles

__global__ __launch_bounds__(256)
void attn_mma(const __nv_bfloat16* __restrict__ Qhi, const __nv_bfloat16* __restrict__ Qlo,
              const __nv_bfloat16* __restrict__ Khi, const __nv_bfloat16* __restrict__ Klo,
              const __nv_bfloat16* __restrict__ Vhi, const __nv_bfloat16* __restrict__ Vlo,
              __nv_bfloat16* __restrict__ Ohi, __nv_bfloat16* __restrict__ Olo)
{
    extern __shared__ char smem[];
    const uint32_t sb = smem_u32(smem);

    const int tid  = threadIdx.x;
    const int lane = tid & 31;
    const int wid  = tid >> 5;
    const int q0   = blockIdx.x << 7;
    const int h    = blockIdx.y;
    const int b    = blockIdx.z;
    const int tok0 = b * SS + q0;
    const int colh = h * HDIM;

    // ---- Q load (once) ----
#pragma unroll
    for (int it = 0; it < 4; it++) {
        const int u   = it * 256 + tid;     // 0..1023
        const int row = u >> 3;
        const int un  = u & 7;
        const size_t g = (size_t)(tok0 + row) * DD + colh + un * 8;
        cp16(sb + SQH + row * PADB + un * 16, Qhi + g);
        cp16(sb + SQL + row * PADB + un * 16, Qlo + g);
    }

    auto load_kv = [&](int t, int st) {
        const uint32_t base = sb + SKV + st * STG;
#pragma unroll
        for (int it = 0; it < 2; it++) {
            const int u   = it * 256 + tid; // 0..511
            const int row = u >> 3;
            const int un  = u & 7;
            const size_t g = (size_t)(b * SS + t * 64 + row) * DD + colh + un * 8;
            const uint32_t so = base + row * PADB + un * 16;
            cp16(so + 0 * KVT, Khi + g);
            cp16(so + 1 * KVT, Klo + g);
            cp16(so + 2 * KVT, Vhi + g);
            cp16(so + 3 * KVT, Vlo + g);
        }
        CP_COMMIT();
    };
    load_kv(0, 0);

    // Fragment address components
    const int wq    = wid * 16;
    const uint32_t aoffQ = (uint32_t)((wq + (lane & 15)) * PADB) + ((lane >> 4) << 4);
    const int nrowK = ((lane >> 4) << 3) + (lane & 7);
    const uint32_t kchunk = (uint32_t)(((lane >> 3) & 1) << 4);
    const int vrow  = (((lane >> 3) & 1) << 3) + (lane & 7);
    const uint32_t vchunk = (uint32_t)((lane >> 4) << 4);

    const float sc = 0.03125f * 1.44269504088896340736f;  // (1/32)*log2(e)

    float m0 = -CUDART_INF_F, m1 = -CUDART_INF_F;
    float l0 = 0.f, l1 = 0.f;
    float acc[8][4];
#pragma unroll
    for (int nf = 0; nf < 8; nf++)
#pragma unroll
        for (int e = 0; e < 4; e++) acc[nf][e] = 0.f;

    for (int t = 0; t < NT; t++) {
        CP_WAIT0();
        __syncthreads();
        if (t + 1 < NT) load_kv(t + 1, (t + 1) & 1);

        const uint32_t kb = sb + SKV + (t & 1) * STG;

        // ---- S = Q K^T (split bf16, 3 MMAs) ----
        float sf[8][4];
#pragma unroll
        for (int nf = 0; nf < 8; nf++)
#pragma unroll
            for (int e = 0; e < 4; e++) sf[nf][e] = 0.f;

#pragma unroll
        for (int ks = 0; ks < 4; ks++) {
            uint32_t qh[4], ql[4];
            ldsm4(qh, sb + SQH + aoffQ + ks * 32);
            ldsm4(ql, sb + SQL + aoffQ + ks * 32);
#pragma unroll
            for (int ng = 0; ng < 4; ng++) {
                const uint32_t ak = kb + (uint32_t)((16 * ng + nrowK) * PADB) +
                                    ks * 32 + kchunk;
                uint32_t kh[4], kl[4];
                ldsm4(kh, ak);             // Khi
                ldsm4(kl, ak + KVT);       // Klo
                mma16816(sf[2 * ng],     qh, kh[0], kh[1]);
                mma16816(sf[2 * ng],     qh, kl[0], kl[1]);
                mma16816(sf[2 * ng],     ql, kh[0], kh[1]);
                mma16816(sf[2 * ng + 1], qh, kh[2], kh[3]);
                mma16816(sf[2 * ng + 1], qh, kl[2], kl[3]);
                mma16816(sf[2 * ng + 1], ql, kh[2], kh[3]);
            }
        }

        // ---- online softmax ----
        float r0 = sf[0][0], r1 = sf[0][2];
#pragma unroll
        for (int nf = 0; nf < 8; nf++) {
            r0 = fmaxf(r0, fmaxf(sf[nf][0], sf[nf][1]));
            r1 = fmaxf(r1, fmaxf(sf[nf][2], sf[nf][3]));
        }
        r0 = fmaxf(r0, __shfl_xor_sync(0xffffffffu, r0, 1));
        r0 = fmaxf(r0, __shfl_xor_sync(0xffffffffu, r0, 2));
        r1 = fmaxf(r1, __shfl_xor_sync(0xffffffffu, r1, 1));
        r1 = fmaxf(r1, __shfl_xor_sync(0xffffffffu, r1, 2));

        const float m0n = fmaxf(m0, r0 * sc);
        const float m1n = fmaxf(m1, r1 * sc);
        const float c0 = exp2f(m0 - m0n);
        const float c1 = exp2f(m1 - m1n);
        m0 = m0n; m1 = m1n;
        l0 *= c0;  l1 *= c1;
#pragma unroll
        for (int nf = 0; nf < 8; nf++) {
            sf[nf][0] = exp2f(fmaf(sf[nf][0], sc, -m0));
            sf[nf][1] = exp2f(fmaf(sf[nf][1], sc, -m0));
            sf[nf][2] = exp2f(fmaf(sf[nf][2], sc, -m1));
            sf[nf][3] = exp2f(fmaf(sf[nf][3], sc, -m1));
            l0 += sf[nf][0] + sf[nf][1];
            l1 += sf[nf][2] + sf[nf][3];
            acc[nf][0] *= c0; acc[nf][1] *= c0;
            acc[nf][2] *= c1; acc[nf][3] *= c1;
        }

        // ---- O += P V (split P and V, 3 MMAs) ----
#pragma unroll
        for (int g = 0; g < 4; g++) {
            uint32_t phi[4], plo[4];
#pragma unroll
            for (int e = 0; e < 4; e++) {
                const int nf = 2 * g + (e >> 1);
                const int j  = (e & 1) << 1;
                const float p0 = sf[nf][j], p1 = sf[nf][j + 1];
                const float h0 = __bfloat162float(__float2bfloat16(p0));
                const float h1 = __bfloat162float(__float2bfloat16(p1));
                phi[e] = pack_bf162(p0, p1);
                plo[e] = pack_bf162(p0 - h0, p1 - h1);
            }
            // reorder: a-frag = {rows(r,k0-7), rows(r+8,k0-7), rows(r,k8-15), rows(r+8,k8-15)}
            // built above as e = {nf=2g:j0, nf=2g:j2, nf=2g+1:j0, nf=2g+1:j2}
            // e0: rows r k0-7 ✓ ; e1: rows r+8 k0-7 ✓ ; e2: rows r k8-15 ✓ ; e3 ✓
#pragma unroll
            for (int dg = 0; dg < 4; dg++) {
                const uint32_t av = kb + 2 * KVT +
                                    (uint32_t)((16 * g + vrow) * PADB) +
                                    dg * 32 + vchunk;
                uint32_t vh[4], vl[4];
                ldsm4t(vh, av);            // Vhi
                ldsm4t(vl, av + KVT);      // Vlo
                mma16816(acc[2 * dg],     phi, vh[0], vh[1]);
                mma16816(acc[2 * dg],     phi, vl[0], vl[1]);
                mma16816(acc[2 * dg],     plo, vh[0], vh[1]);
                mma16816(acc[2 * dg + 1], phi, vh[2], vh[3]);
                mma16816(acc[2 * dg + 1], phi, vl[2], vl[3]);
                mma16816(acc[2 * dg + 1], plo, vh[2], vh[3]);
            }
        }
        __syncthreads();
    }

    // final l reduction across quad
    l0 += __shfl_xor_sync(0xffffffffu, l0, 1);
    l0 += __shfl_xor_sync(0xffffffffu, l0, 2);
    l1 += __shfl_xor_sync(0xffffffffu, l1, 1);
    l1 += __shfl_xor_sync(0xffffffffu, l1, 2);
    const float i0 = 1.f / l0;
    const float i1 = 1.f / l1;

    const int rowa = tok0 + wq + (lane >> 2);
    const int colb = colh + ((lane & 3) << 1);
#pragma unroll
    for (int nf = 0; nf < 8; nf++) {
        const int gc = colb + nf * 8;
        {
            const float v0 = acc[nf][0] * i0, v1 = acc[nf][1] * i0;
            const float h0 = __bfloat162float(__float2bfloat16(v0));
            const float h1 = __bfloat162float(__float2bfloat16(v1));
            const size_t off = (size_t)rowa * DD + gc;
            *(uint32_t*)(Ohi + off) = pack_bf162(v0, v1);
            *(uint32_t*)(Olo + off) = pack_bf162(v0 - h0, v1 - h1);
        }
        {
            const float v0 = acc[nf][2] * i1, v1 = acc[nf][3] * i1;
            const float h0 = __bfloat162float(__float2bfloat16(v0));
            const float h1 = __bfloat162float(__float2bfloat16(v1));
            const size_t off = (size_t)(rowa + 8) * DD + gc;
            *(uint32_t*)(Ohi + off) = pack_bf162(v0, v1);
            *(uint32_t*)(Olo + off) = pack_bf162(v0 - h0, v1 - h1);
        }
    }
}

// ---------------------------------------------------------------------------
extern "C" void kernel_launch(void* const* d_in, const int* in_sizes, int n_in,
                              void* d_out, int out_size)
{
    const float* values = (const float*)d_in[0];
    const float* keys   = (const float*)d_in[1];
    const float* query  = (const float*)d_in[2];
    const float* Wv     = (const float*)d_in[3];
    const float* Wk     = (const float*)d_in[4];
    const float* Wq     = (const float*)d_in[5];
    const float* Wo     = (const float*)d_in[6];
    const float* bo     = (const float*)d_in[7];
    float* out = (float*)d_out;

    __nv_bfloat16 *ahi, *alo, *whi, *wlo, *qhi, *qlo, *khi, *klo, *vhi, *vlo;
    cudaGetSymbolAddress((void**)&ahi, g_ahi);
    cudaGetSymbolAddress((void**)&alo, g_alo);
    cudaGetSymbolAddress((void**)&whi, g_whi);
    cudaGetSymbolAddress((void**)&wlo, g_wlo);
    cudaGetSymbolAddress((void**)&qhi, g_qhi);
    cudaGetSymbolAddress((void**)&qlo, g_qlo);
    cudaGetSymbolAddress((void**)&khi, g_khi);
    cudaGetSymbolAddress((void**)&klo, g_klo);
    cudaGetSymbolAddress((void**)&vhi, g_vhi);
    cudaGetSymbolAddress((void**)&vlo, g_vlo);

    cudaFuncSetAttribute(gemm_mma<false, true>,
                         cudaFuncAttributeMaxDynamicSharedMemorySize, GEMM_SMEM);
    cudaFuncSetAttribute(gemm_mma<true, false>,
                         cudaFuncAttributeMaxDynamicSharedMemorySize, GEMM_SMEM);
    cudaFuncSetAttribute(attn_mma,
                         cudaFuncAttributeMaxDynamicSharedMemorySize, ATTN_SMEM);

    const int W4 = DD * DD / 4;
    const int A4 = MTOK * DD / 4;

    split_f32<<<W4 / 256, 256>>>(Wq, whi + 0 * DD * DD, wlo + 0 * DD * DD, W4);
    split_f32<<<W4 / 256, 256>>>(Wk, whi + 1 * DD * DD, wlo + 1 * DD * DD, W4);
    split_f32<<<W4 / 256, 256>>>(Wv, whi + 2 * DD * DD, wlo + 2 * DD * DD, W4);
    split_f32<<<W4 / 256, 256>>>(Wo, whi + 3 * DD * DD, wlo + 3 * DD * DD, W4);

    dim3 gg(DD / 128, MTOK / 128);    // (8, 64)

    split_f32<<<A4 / 256, 256>>>(query, ahi, alo, A4);
    gemm_mma<false, true><<<gg, 256, GEMM_SMEM>>>(ahi, alo, whi + 0 * DD * DD,
        wlo + 0 * DD * DD, nullptr, nullptr, qhi, qlo);
    split_f32<<<A4 / 256, 256>>>(keys, ahi, alo, A4);
    gemm_mma<false, true><<<gg, 256, GEMM_SMEM>>>(ahi, alo, whi + 1 * DD * DD,
        wlo + 1 * DD * DD, nullptr, nullptr, khi, klo);
    split_f32<<<A4 / 256, 256>>>(values, ahi, alo, A4);
    gemm_mma<false, true><<<gg, 256, GEMM_SMEM>>>(ahi, alo, whi + 2 * DD * DD,
        wlo + 2 * DD * DD, nullptr, nullptr, vhi, vlo);

    dim3 ga(SS / 128, HH, BB);        // (16, 16, 4)
    attn_mma<<<ga, 256, ATTN_SMEM>>>(qhi, qlo, khi, klo, vhi, vlo, ahi, alo);

    gemm_mma<true, false><<<gg, 256, GEMM_SMEM>>>(ahi, alo, whi + 3 * DD * DD,
        wlo + 3 * DD * DD, bo, out, nullptr, nullptr);
}

// round 8
// speedup vs baseline: 3.2332x; 1.0156x over previous
#include <cuda_runtime.h>
#include <cuda_bf16.h>
#include <math_constants.h>
#include <cstdint>

// Problem constants (fixed by setup_inputs)
#define BB   4
#define SS   2048
#define DD   1024
#define HH   16
#define HDIM 64
#define MTOK (BB * SS)          // 8192 tokens

// ---------------------------------------------------------------------------
// Scratch (static device globals: allocation-free, graph-capturable)
// ---------------------------------------------------------------------------
__device__ __align__(16) __nv_bfloat16 g_ahi[MTOK * DD];   // query split / attn out hi
__device__ __align__(16) __nv_bfloat16 g_alo[MTOK * DD];
__device__ __align__(16) __nv_bfloat16 g_bhi[MTOK * DD];   // keys split
__device__ __align__(16) __nv_bfloat16 g_blo[MTOK * DD];
__device__ __align__(16) __nv_bfloat16 g_chi[MTOK * DD];   // values split
__device__ __align__(16) __nv_bfloat16 g_clo[MTOK * DD];
__device__ __align__(16) __nv_bfloat16 g_whi[4 * DD * DD];
__device__ __align__(16) __nv_bfloat16 g_wlo[4 * DD * DD];
__device__ __align__(16) __nv_bfloat16 g_qhi[MTOK * DD];
__device__ __align__(16) __nv_bfloat16 g_qlo[MTOK * DD];
__device__ __align__(16) __nv_bfloat16 g_khi[MTOK * DD];
__device__ __align__(16) __nv_bfloat16 g_klo[MTOK * DD];
__device__ __align__(16) __nv_bfloat16 g_vhi[MTOK * DD];
__device__ __align__(16) __nv_bfloat16 g_vlo[MTOK * DD];

// ---------------------------------------------------------------------------
// Base-ISA helpers (sm_103 base target; tcgen05 is ptxas-rejected here)
// ---------------------------------------------------------------------------
__device__ __forceinline__ uint32_t smem_u32(const void* p) {
    uint32_t a;
    asm("{ .reg .u64 t; cvta.to.shared.u64 t, %1; cvt.u32.u64 %0, t; }"
        : "=r"(a) : "l"(p));
    return a;
}
__device__ __forceinline__ void ldsm4(uint32_t (&r)[4], uint32_t addr) {
    asm volatile("ldmatrix.sync.aligned.m8n8.x4.shared.b16 {%0,%1,%2,%3}, [%4];"
                 : "=r"(r[0]), "=r"(r[1]), "=r"(r[2]), "=r"(r[3]) : "r"(addr));
}
__device__ __forceinline__ void ldsm4t(uint32_t (&r)[4], uint32_t addr) {
    asm volatile("ldmatrix.sync.aligned.m8n8.x4.trans.shared.b16 {%0,%1,%2,%3}, [%4];"
                 : "=r"(r[0]), "=r"(r[1]), "=r"(r[2]), "=r"(r[3]) : "r"(addr));
}
__device__ __forceinline__ void mma16816(float (&d)[4], const uint32_t (&a)[4],
                                         uint32_t b0, uint32_t b1) {
    asm volatile(
        "mma.sync.aligned.m16n8k16.row.col.f32.bf16.bf16.f32 "
        "{%0,%1,%2,%3}, {%4,%5,%6,%7}, {%8,%9}, {%0,%1,%2,%3};"
        : "+f"(d[0]), "+f"(d[1]), "+f"(d[2]), "+f"(d[3])
        : "r"(a[0]), "r"(a[1]), "r"(a[2]), "r"(a[3]), "r"(b0), "r"(b1));
}
__device__ __forceinline__ void cp16(uint32_t saddr, const void* g) {
    asm volatile("cp.async.cg.shared.global [%0], [%1], 16;"
                 :: "r"(saddr), "l"(g) : "memory");
}
#define CP_COMMIT() asm volatile("cp.async.commit_group;" ::: "memory")
#define CP_WAIT0()  asm volatile("cp.async.wait_group 0;" ::: "memory")
#define CP_WAIT1()  asm volatile("cp.async.wait_group 1;" ::: "memory")

__device__ __forceinline__ uint32_t pack_bf162(float lo, float hi) {
    __nv_bfloat162 h = __floats2bfloat162_rn(lo, hi);
    return *reinterpret_cast<uint32_t*>(&h);
}

// ---------------------------------------------------------------------------
// fp32 -> bf16 hi/lo split (elementwise); batched variants
// ---------------------------------------------------------------------------
__device__ __forceinline__ void split_body(const float* __restrict__ x,
                                           __nv_bfloat16* __restrict__ hi,
                                           __nv_bfloat16* __restrict__ lo, int i)
{
    float4 v = ((const float4*)x)[i];
    float vv[4] = {v.x, v.y, v.z, v.w};
    __nv_bfloat16 h[4], l[4];
#pragma unroll
    for (int j = 0; j < 4; j++) {
        h[j] = __float2bfloat16(vv[j]);
        l[j] = __float2bfloat16(vv[j] - __bfloat162float(h[j]));
    }
    __nv_bfloat162 h0; h0.x = h[0]; h0.y = h[1];
    __nv_bfloat162 h1; h1.x = h[2]; h1.y = h[3];
    __nv_bfloat162 l0; l0.x = l[0]; l0.y = l[1];
    __nv_bfloat162 l1; l1.x = l[2]; l1.y = l[3];
    ((__nv_bfloat162*)hi)[i * 2 + 0] = h0;
    ((__nv_bfloat162*)hi)[i * 2 + 1] = h1;
    ((__nv_bfloat162*)lo)[i * 2 + 0] = l0;
    ((__nv_bfloat162*)lo)[i * 2 + 1] = l1;
}

#define W4 (DD * DD / 4)
#define A4 (MTOK * DD / 4)

__global__ __launch_bounds__(256)
void split_w4(const float* __restrict__ w0, const float* __restrict__ w1,
              const float* __restrict__ w2, const float* __restrict__ w3,
              __nv_bfloat16* __restrict__ hi, __nv_bfloat16* __restrict__ lo)
{
    const int blk = blockIdx.x;
    const int seg = blk >> 10;                        // W4/256 = 1024 blocks/seg
    const int i   = (blk & 1023) * 256 + threadIdx.x; // 0..W4-1
    const float* src = (seg == 0) ? w0 : (seg == 1) ? w1 : (seg == 2) ? w2 : w3;
    split_body(src, hi + (size_t)seg * DD * DD, lo + (size_t)seg * DD * DD, i);
}

__global__ __launch_bounds__(256)
void split_in3(const float* __restrict__ q, const float* __restrict__ k,
               const float* __restrict__ v,
               __nv_bfloat16* __restrict__ qh, __nv_bfloat16* __restrict__ ql,
               __nv_bfloat16* __restrict__ kh, __nv_bfloat16* __restrict__ kl,
               __nv_bfloat16* __restrict__ vh, __nv_bfloat16* __restrict__ vl)
{
    const int blk = blockIdx.x;                       // A4/256 = 8192 blocks/seg
    const int seg = blk >> 13;
    const int i   = (blk & 8191) * 256 + threadIdx.x;
    if (seg == 0)      split_body(q, qh, ql, i);
    else if (seg == 1) split_body(k, kh, kl, i);
    else               split_body(v, vh, vl, i);
}

// ---------------------------------------------------------------------------
// mma.sync split-bf16 GEMM:  C[m,n] = sum_k A[m,k]*W[n,k] (+bias[n])
// CTA tile 128x128, 8 warps (2m x 4n), warp tile 64x32, K chunk = 32 bf16.
// Smem: per stage 2 arrays (A, B); each 128 rows x 128B = [hi 64B | lo 64B],
// XOR-swizzled (unit ^= row&7) -> conflict-free ldmatrix, zero padding.
// 3-stage cp.async pipeline, wait_group 1.
// ---------------------------------------------------------------------------
#define NSTG        3
#define TILE_AB     16384               // 128 rows * 128B
#define STAGE_BYTES (2 * TILE_AB)       // 32768
#define GEMM_SMEM   (NSTG * STAGE_BYTES)// 98304
#define NKC         (DD / 32)           // 32 chunks

template <bool BIAS, bool SPLIT>
__global__ __launch_bounds__(256)
void gemm_mma(const __nv_bfloat16* __restrict__ Ahi, const __nv_bfloat16* __restrict__ Alo,
              const __nv_bfloat16* __restrict__ Whi, const __nv_bfloat16* __restrict__ Wlo,
              const float* __restrict__ bias, float* __restrict__ C,
              __nv_bfloat16* __restrict__ Chi, __nv_bfloat16* __restrict__ Clo)
{
    extern __shared__ char smem[];
    const uint32_t sb = smem_u32(smem);

    const int tid   = threadIdx.x;
    const int lane  = tid & 31;
    const int wid   = tid >> 5;
    const int warpM = wid >> 2;
    const int warpN = wid & 3;
    const int m0 = blockIdx.y << 7;
    const int n0 = blockIdx.x << 7;

    auto load_stage = [&](int kc, int st) {
        const uint32_t stb = sb + st * STAGE_BYTES;
#pragma unroll
        for (int t = 0; t < 2; t++) {           // 0 = A, 1 = B(W)
            const int base_row = t ? n0 : m0;
            const __nv_bfloat16* hi = t ? Whi : Ahi;
            const __nv_bfloat16* lo = t ? Wlo : Alo;
#pragma unroll
            for (int p = 0; p < 4; p++) {
                const int u   = p * 256 + tid;  // 0..1023
                const int row = u >> 3;
                const int un  = u & 7;          // 0-3 hi, 4-7 lo
                const __nv_bfloat16* src = (un < 4)
                    ? hi + (size_t)(base_row + row) * DD + kc * 32 + un * 8
                    : lo + (size_t)(base_row + row) * DD + kc * 32 + (un - 4) * 8;
                cp16(stb + t * TILE_AB + row * 128 + ((un ^ (row & 7)) << 4), src);
            }
        }
        CP_COMMIT();
    };

    float d[4][4][4];
#pragma unroll
    for (int mf = 0; mf < 4; mf++)
#pragma unroll
        for (int nf = 0; nf < 4; nf++)
#pragma unroll
            for (int e = 0; e < 4; e++) d[mf][nf][e] = 0.f;

    load_stage(0, 0);
    load_stage(1, 1);

    // Fragment address components
    const int arow  = warpM * 64 + (lane & 15);
    const int ahalf = lane >> 4;                 // k +8 half
    const int mi    = lane >> 3;
    const int brow  = warpN * 32 + ((mi >> 1) << 3) + (lane & 7);
    const int bhalf = mi & 1;

    for (int kc = 0; kc < NKC; kc++) {
        if (kc == NKC - 1) { CP_WAIT0(); } else { CP_WAIT1(); }
        __syncthreads();
        if (kc + 2 < NKC) load_stage(kc + 2, (kc + 2) % 3);

        const uint32_t stA = sb + (kc % 3) * STAGE_BYTES;
        const uint32_t stB = stA + TILE_AB;
#pragma unroll
        for (int s = 0; s < 2; s++) {
            uint32_t ahi[4][4], alo[4][4];
#pragma unroll
            for (int mf = 0; mf < 4; mf++) {
                const int r = arow + mf * 16;
                const int u = (s << 1) + ahalf;
                const int uh = u ^ (r & 7);
                ldsm4(ahi[mf], stA + r * 128 + (uh << 4));
                ldsm4(alo[mf], stA + r * 128 + ((uh ^ 4) << 4));
            }
            uint32_t bhi[2][4], blo[2][4];
#pragma unroll
            for (int nfp = 0; nfp < 2; nfp++) {
                const int r = brow + nfp * 16;
                const int u = (s << 1) + bhalf;
                const int uh = u ^ (r & 7);
                ldsm4(bhi[nfp], stB + r * 128 + (uh << 4));
                ldsm4(blo[nfp], stB + r * 128 + ((uh ^ 4) << 4));
            }
#pragma unroll
            for (int mf = 0; mf < 4; mf++) {
#pragma unroll
                for (int nf = 0; nf < 4; nf++) {
                    const int p = nf >> 1, q = (nf & 1) << 1;
                    mma16816(d[mf][nf], ahi[mf], bhi[p][q], bhi[p][q + 1]);
                    mma16816(d[mf][nf], ahi[mf], blo[p][q], blo[p][q + 1]);
                    mma16816(d[mf][nf], alo[mf], bhi[p][q], bhi[p][q + 1]);
                }
            }
        }
    }

    // Epilogue
#pragma unroll
    for (int mf = 0; mf < 4; mf++) {
        const int gm = m0 + warpM * 64 + mf * 16 + (lane >> 2);
#pragma unroll
        for (int nf = 0; nf < 4; nf++) {
            const int gn = n0 + warpN * 32 + nf * 8 + ((lane & 3) << 1);
            if (SPLIT) {
#pragma unroll
                for (int hrow = 0; hrow < 2; hrow++) {
                    const size_t off = (size_t)(gm + hrow * 8) * DD + gn;
                    const float v0 = d[mf][nf][hrow * 2 + 0];
                    const float v1 = d[mf][nf][hrow * 2 + 1];
                    const float h0 = __bfloat162float(__float2bfloat16(v0));
                    const float h1 = __bfloat162float(__float2bfloat16(v1));
                    *(uint32_t*)(Chi + off) = pack_bf162(v0, v1);
                    *(uint32_t*)(Clo + off) = pack_bf162(v0 - h0, v1 - h1);
                }
            } else {
                float2 v0 = make_float2(d[mf][nf][0], d[mf][nf][1]);
                float2 v1 = make_float2(d[mf][nf][2], d[mf][nf][3]);
                if (BIAS) {
                    const float b0 = bias[gn], b1 = bias[gn + 1];
                    v0.x += b0; v0.y += b1;
                    v1.x += b0; v1.y += b1;
                }
                *(float2*)(C + (size_t)gm * DD + gn)       = v0;
                *(float2*)(C + (size_t)(gm + 8) * DD + gn) = v1;
            }
        }
    }
}

// ---------------------------------------------------------------------------
// Flash attention on mma.sync, split-bf16 QK^T and P,V.
// CTA: 256 Q rows for one (b,h), 512 threads (16 warps x 16 rows).
// KV tiles of 64, cp.async double-buffered. Output written split (hi/lo).
// ---------------------------------------------------------------------------
#define ATHREADS 512
#define PADB  144
#define SQH   0
#define SQL   (256 * PADB)                 // 36864
#define SKV   (2 * 256 * PADB)             // 73728
#define KVT   (64 * PADB)                  // 9216 per array
#define STG   (4 * KVT)                    // 36864 per stage
#define ATTN_SMEM (SKV + 2 * STG)          // 147456
#define NT    (SS / 64)                    // 32 kv tiles

__global__ __launch_bounds__(ATHREADS)
void attn_mma(const __nv_bfloat16* __restrict__ Qhi, const __nv_bfloat16* __restrict__ Qlo,
              const __nv_bfloat16* __restrict__ Khi, const __nv_bfloat16* __restrict__ Klo,
              const __nv_bfloat16* __restrict__ Vhi, const __nv_bfloat16* __restrict__ Vlo,
              __nv_bfloat16* __restrict__ Ohi, __nv_bfloat16* __restrict__ Olo)
{
    extern __shared__ char smem[];
    const uint32_t sb = smem_u32(smem);

    const int tid  = threadIdx.x;
    const int lane = tid & 31;
    const int wid  = tid >> 5;
    const int q0   = blockIdx.x << 8;      // 256 rows per CTA
    const int h    = blockIdx.y;
    const int b    = blockIdx.z;
    const int tok0 = b * SS + q0;
    const int colh = h * HDIM;

    // ---- Q load (once): 256 rows x 8 units, hi+lo ----
#pragma unroll
    for (int it = 0; it < 4; it++) {
        const int u   = it * ATHREADS + tid;   // 0..2047
        const int row = u >> 3;
        const int un  = u & 7;
        const size_t g = (size_t)(tok0 + row) * DD + colh + un * 8;
        cp16(sb + SQH + row * PADB + un * 16, Qhi + g);
        cp16(sb + SQL + row * PADB + un * 16, Qlo + g);
    }

    auto load_kv = [&](int t, int st) {
        const uint32_t base = sb + SKV + st * STG;
        const int row = tid >> 3;              // 0..63
        const int un  = tid & 7;
        const size_t g = (size_t)(b * SS + t * 64 + row) * DD + colh + un * 8;
        const uint32_t so = base + row * PADB + un * 16;
        cp16(so + 0 * KVT, Khi + g);
        cp16(so + 1 * KVT, Klo + g);
        cp16(so + 2 * KVT, Vhi + g);
        cp16(so + 3 * KVT, Vlo + g);
        CP_COMMIT();
    };
    load_kv(0, 0);

    // Fragment address components
    const int wq    = wid * 16;
    const uint32_t aoffQ = (uint32_t)((wq + (lane & 15)) * PADB) + ((lane >> 4) << 4);
    const int nrowK = ((lane >> 4) << 3) + (lane & 7);
    const uint32_t kchunk = (uint32_t)(((lane >> 3) & 1) << 4);
    const int vrow  = (((lane >> 3) & 1) << 3) + (lane & 7);
    const uint32_t vchunk = (uint32_t)((lane >> 4) << 4);

    const float sc = 0.03125f * 1.44269504088896340736f;  // (1/32)*log2(e)

    float m0 = -CUDART_INF_F, m1 = -CUDART_INF_F;
    float l0 = 0.f, l1 = 0.f;
    float acc[8][4];
#pragma unroll
    for (int nf = 0; nf < 8; nf++)
#pragma unroll
        for (int e = 0; e < 4; e++) acc[nf][e] = 0.f;

    for (int t = 0; t < NT; t++) {
        CP_WAIT0();
        __syncthreads();
        if (t + 1 < NT) load_kv(t + 1, (t + 1) & 1);

        const uint32_t kb = sb + SKV + (t & 1) * STG;

        // ---- S = Q K^T (split bf16, 3 MMAs) ----
        float sf[8][4];
#pragma unroll
        for (int nf = 0; nf < 8; nf++)
#pragma unroll
            for (int e = 0; e < 4; e++) sf[nf][e] = 0.f;

#pragma unroll
        for (int ks = 0; ks < 4; ks++) {
            uint32_t qh[4], ql[4];
            ldsm4(qh, sb + SQH + aoffQ + ks * 32);
            ldsm4(ql, sb + SQL + aoffQ + ks * 32);
#pragma unroll
            for (int ng = 0; ng < 4; ng++) {
                const uint32_t ak = kb + (uint32_t)((16 * ng + nrowK) * PADB) +
                                    ks * 32 + kchunk;
                uint32_t kh[4], kl[4];
                ldsm4(kh, ak);             // Khi
                ldsm4(kl, ak + KVT);       // Klo
                mma16816(sf[2 * ng],     qh, kh[0], kh[1]);
                mma16816(sf[2 * ng],     qh, kl[0], kl[1]);
                mma16816(sf[2 * ng],     ql, kh[0], kh[1]);
                mma16816(sf[2 * ng + 1], qh, kh[2], kh[3]);
                mma16816(sf[2 * ng + 1], qh, kl[2], kl[3]);
                mma16816(sf[2 * ng + 1], ql, kh[2], kh[3]);
            }
        }

        // ---- online softmax ----
        float r0 = sf[0][0], r1 = sf[0][2];
#pragma unroll
        for (int nf = 0; nf < 8; nf++) {
            r0 = fmaxf(r0, fmaxf(sf[nf][0], sf[nf][1]));
            r1 = fmaxf(r1, fmaxf(sf[nf][2], sf[nf][3]));
        }
        r0 = fmaxf(r0, __shfl_xor_sync(0xffffffffu, r0, 1));
        r0 = fmaxf(r0, __shfl_xor_sync(0xffffffffu, r0, 2));
        r1 = fmaxf(r1, __shfl_xor_sync(0xffffffffu, r1, 1));
        r1 = fmaxf(r1, __shfl_xor_sync(0xffffffffu, r1, 2));

        const float m0n = fmaxf(m0, r0 * sc);
        const float m1n = fmaxf(m1, r1 * sc);
        const float c0 = exp2f(m0 - m0n);
        const float c1 = exp2f(m1 - m1n);
        m0 = m0n; m1 = m1n;
        l0 *= c0;  l1 *= c1;
#pragma unroll
        for (int nf = 0; nf < 8; nf++) {
            sf[nf][0] = exp2f(fmaf(sf[nf][0], sc, -m0));
            sf[nf][1] = exp2f(fmaf(sf[nf][1], sc, -m0));
            sf[nf][2] = exp2f(fmaf(sf[nf][2], sc, -m1));
            sf[nf][3] = exp2f(fmaf(sf[nf][3], sc, -m1));
            l0 += sf[nf][0] + sf[nf][1];
            l1 += sf[nf][2] + sf[nf][3];
            acc[nf][0] *= c0; acc[nf][1] *= c0;
            acc[nf][2] *= c1; acc[nf][3] *= c1;
        }

        // ---- O += P V (split P and V, 3 MMAs) ----
#pragma unroll
        for (int g = 0; g < 4; g++) {
            uint32_t phi[4], plo[4];
#pragma unroll
            for (int e = 0; e < 4; e++) {
                const int nf = 2 * g + (e >> 1);
                const int j  = (e & 1) << 1;
                const float p0 = sf[nf][j], p1 = sf[nf][j + 1];
                const float h0 = __bfloat162float(__float2bfloat16(p0));
                const float h1 = __bfloat162float(__float2bfloat16(p1));
                phi[e] = pack_bf162(p0, p1);
                plo[e] = pack_bf162(p0 - h0, p1 - h1);
            }
#pragma unroll
            for (int dg = 0; dg < 4; dg++) {
                const uint32_t av = kb + 2 * KVT +
                                    (uint32_t)((16 * g + vrow) * PADB) +
                                    dg * 32 + vchunk;
                uint32_t vh[4], vl[4];
                ldsm4t(vh, av);            // Vhi
                ldsm4t(vl, av + KVT);      // Vlo
                mma16816(acc[2 * dg],     phi, vh[0], vh[1]);
                mma16816(acc[2 * dg],     phi, vl[0], vl[1]);
                mma16816(acc[2 * dg],     plo, vh[0], vh[1]);
                mma16816(acc[2 * dg + 1], phi, vh[2], vh[3]);
                mma16816(acc[2 * dg + 1], phi, vl[2], vl[3]);
                mma16816(acc[2 * dg + 1], plo, vh[2], vh[3]);
            }
        }
        __syncthreads();
    }

    // final l reduction across quad
    l0 += __shfl_xor_sync(0xffffffffu, l0, 1);
    l0 += __shfl_xor_sync(0xffffffffu, l0, 2);
    l1 += __shfl_xor_sync(0xffffffffu, l1, 1);
    l1 += __shfl_xor_sync(0xffffffffu, l1, 2);
    const float i0 = 1.f / l0;
    const float i1 = 1.f / l1;

    const int rowa = tok0 + wq + (lane >> 2);
    const int colb = colh + ((lane & 3) << 1);
#pragma unroll
    for (int nf = 0; nf < 8; nf++) {
        const int gc = colb + nf * 8;
        {
            const float v0 = acc[nf][0] * i0, v1 = acc[nf][1] * i0;
            const float h0 = __bfloat162float(__float2bfloat16(v0));
            const float h1 = __bfloat162float(__float2bfloat16(v1));
            const size_t off = (size_t)rowa * DD + gc;
            *(uint32_t*)(Ohi + off) = pack_bf162(v0, v1);
            *(uint32_t*)(Olo + off) = pack_bf162(v0 - h0, v1 - h1);
        }
        {
            const float v0 = acc[nf][2] * i1, v1 = acc[nf][3] * i1;
            const float h0 = __bfloat162float(__float2bfloat16(v0));
            const float h1 = __bfloat162float(__float2bfloat16(v1));
            const size_t off = (size_t)(rowa + 8) * DD + gc;
            *(uint32_t*)(Ohi + off) = pack_bf162(v0, v1);
            *(uint32_t*)(Olo + off) = pack_bf162(v0 - h0, v1 - h1);
        }
    }
}

// ---------------------------------------------------------------------------
extern "C" void kernel_launch(void* const* d_in, const int* in_sizes, int n_in,
                              void* d_out, int out_size)
{
    const float* values = (const float*)d_in[0];
    const float* keys   = (const float*)d_in[1];
    const float* query  = (const float*)d_in[2];
    const float* Wv     = (const float*)d_in[3];
    const float* Wk     = (const float*)d_in[4];
    const float* Wq     = (const float*)d_in[5];
    const float* Wo     = (const float*)d_in[6];
    const float* bo     = (const float*)d_in[7];
    float* out = (float*)d_out;

    __nv_bfloat16 *ahi, *alo, *bhi, *blo, *chi, *clo, *whi, *wlo;
    __nv_bfloat16 *qhi, *qlo, *khi, *klo, *vhi, *vlo;
    cudaGetSymbolAddress((void**)&ahi, g_ahi);
    cudaGetSymbolAddress((void**)&alo, g_alo);
    cudaGetSymbolAddress((void**)&bhi, g_bhi);
    cudaGetSymbolAddress((void**)&blo, g_blo);
    cudaGetSymbolAddress((void**)&chi, g_chi);
    cudaGetSymbolAddress((void**)&clo, g_clo);
    cudaGetSymbolAddress((void**)&whi, g_whi);
    cudaGetSymbolAddress((void**)&wlo, g_wlo);
    cudaGetSymbolAddress((void**)&qhi, g_qhi);
    cudaGetSymbolAddress((void**)&qlo, g_qlo);
    cudaGetSymbolAddress((void**)&khi, g_khi);
    cudaGetSymbolAddress((void**)&klo, g_klo);
    cudaGetSymbolAddress((void**)&vhi, g_vhi);
    cudaGetSymbolAddress((void**)&vlo, g_vlo);

    cudaFuncSetAttribute(gemm_mma<false, true>,
                         cudaFuncAttributeMaxDynamicSharedMemorySize, GEMM_SMEM);
    cudaFuncSetAttribute(gemm_mma<true, false>,
                         cudaFuncAttributeMaxDynamicSharedMemorySize, GEMM_SMEM);
    cudaFuncSetAttribute(attn_mma,
                         cudaFuncAttributeMaxDynamicSharedMemorySize, ATTN_SMEM);

    // All splits batched: one weight launch, one input launch
    split_w4<<<4 * (W4 / 256), 256>>>(Wq, Wk, Wv, Wo, whi, wlo);
    split_in3<<<3 * (A4 / 256), 256>>>(query, keys, values,
                                       ahi, alo, bhi, blo, chi, clo);

    dim3 gg(DD / 128, MTOK / 128);    // (8, 64)
    gemm_mma<false, true><<<gg, 256, GEMM_SMEM>>>(ahi, alo, whi + 0 * DD * DD,
        wlo + 0 * DD * DD, nullptr, nullptr, qhi, qlo);
    gemm_mma<false, true><<<gg, 256, GEMM_SMEM>>>(bhi, blo, whi + 1 * DD * DD,
        wlo + 1 * DD * DD, nullptr, nullptr, khi, klo);
    gemm_mma<false, true><<<gg, 256, GEMM_SMEM>>>(chi, clo, whi + 2 * DD * DD,
        wlo + 2 * DD * DD, nullptr, nullptr, vhi, vlo);

    dim3 ga(SS / 256, HH, BB);        // (8, 16, 4)
    attn_mma<<<ga, ATHREADS, ATTN_SMEM>>>(qhi, qlo, khi, klo, vhi, vlo, ahi, alo);

    gemm_mma<true, false><<<gg, 256, GEMM_SMEM>>>(ahi, alo, whi + 3 * DD * DD,
        wlo + 3 * DD * DD, bo, out, nullptr, nullptr);
}